// round 1
// baseline (speedup 1.0000x reference)
#include <cuda_runtime.h>
#include <cuda_bf16.h>

// Problem constants (fixed by the reference)
#define NN      8192      // total nodes
#define NODE    256       // nodes per env block
#define DEG     16        // max degree
#define NFEAT   128
#define NHID    256
#define NCLASS  64

// Scratch (device globals; no allocation allowed)
__device__ float g_H[NN * NHID];    // x @ W1
__device__ float g_A[NN * NHID];    // relu(adj @ H)
__device__ float g_T[NN * NCLASS];  // g_A @ W2

// ---------------------------------------------------------------------------
// Register-tiled SGEMM: C[M,N] = A[M,K] @ B[K,N]
// BM=BN=64, BK=16, 256 threads, 4x4 per-thread tile. Requires M%64==0,
// N%64==0 or N==64, K%16==0, all pointers 16B aligned (true here).
// ---------------------------------------------------------------------------
#define BM 64
#define BN 64
#define BK 16

__global__ __launch_bounds__(256)
void sgemm_kernel(const float* __restrict__ A, const float* __restrict__ B,
                  float* __restrict__ C, int M, int Nn, int K)
{
    __shared__ float As[BK][BM];      // A tile, transposed (k-major)
    __shared__ float Bs[BK][BN];

    const int tid  = threadIdx.x;
    const int brow = blockIdx.x * BM;
    const int bcol = blockIdx.y * BN;

    const int tx = tid & 15;          // 0..15 -> output col group
    const int ty = tid >> 4;          // 0..15 -> output row group

    // A load mapping: thread t loads float4 from row (t/4), col seg (t%4)*4
    const int ar = tid >> 2;          // 0..63
    const int ac = (tid & 3) << 2;    // 0,4,8,12
    // B load mapping: thread t loads float4 from row (t/16), col (t%16)*4
    const int br = tid >> 4;          // 0..15
    const int bc = (tid & 15) << 2;   // 0..60

    float acc[4][4] = {};

    for (int k0 = 0; k0 < K; k0 += BK) {
        float4 av = *reinterpret_cast<const float4*>(A + (size_t)(brow + ar) * K + k0 + ac);
        As[ac + 0][ar] = av.x;
        As[ac + 1][ar] = av.y;
        As[ac + 2][ar] = av.z;
        As[ac + 3][ar] = av.w;
        float4 bv = *reinterpret_cast<const float4*>(B + (size_t)(k0 + br) * Nn + bcol + bc);
        *reinterpret_cast<float4*>(&Bs[br][bc]) = bv;
        __syncthreads();

#pragma unroll
        for (int k = 0; k < BK; ++k) {
            float4 ra = *reinterpret_cast<const float4*>(&As[k][ty << 2]);
            float4 rb = *reinterpret_cast<const float4*>(&Bs[k][tx << 2]);
            float a4[4] = {ra.x, ra.y, ra.z, ra.w};
            float b4[4] = {rb.x, rb.y, rb.z, rb.w};
#pragma unroll
            for (int i = 0; i < 4; ++i)
#pragma unroll
                for (int j = 0; j < 4; ++j)
                    acc[i][j] = fmaf(a4[i], b4[j], acc[i][j]);
        }
        __syncthreads();
    }

#pragma unroll
    for (int i = 0; i < 4; ++i) {
        float4 v = make_float4(acc[i][0], acc[i][1], acc[i][2], acc[i][3]);
        *reinterpret_cast<float4*>(C + (size_t)(brow + (ty << 2) + i) * Nn + bcol + (tx << 2)) = v;
    }
}

// ---------------------------------------------------------------------------
// Layer-1 aggregation + ReLU: out[i,:] = relu( sum_{distinct valid j} H[base+j,:] )
// One block (256 threads) per node; thread = one of NHID columns.
// ---------------------------------------------------------------------------
__global__ __launch_bounds__(256)
void agg_relu_kernel(const float* __restrict__ Hin, const int* __restrict__ edge,
                     float* __restrict__ Hout)
{
    const int node = blockIdx.x;
    const int col  = threadIdx.x;
    const int base = (node / NODE) * NODE;

    __shared__ int s_idx[DEG];
    __shared__ int s_keep[DEG];

    if (threadIdx.x < DEG)
        s_idx[threadIdx.x] = edge[node * DEG + threadIdx.x];
    __syncthreads();

    if (threadIdx.x < DEG) {
        int e = s_idx[threadIdx.x];
        int k = (e >= 0) ? 1 : 0;
        for (int p = 0; p < threadIdx.x; ++p)
            if (s_idx[p] == e) k = 0;       // dedup: adjacency is 0/1
        s_keep[threadIdx.x] = k;
    }
    __syncthreads();

    float s = 0.0f;
#pragma unroll
    for (int e = 0; e < DEG; ++e) {
        if (s_keep[e])
            s += Hin[(size_t)(base + s_idx[e]) * NHID + col];
    }
    Hout[(size_t)node * NHID + col] = fmaxf(s, 0.0f);
}

// ---------------------------------------------------------------------------
// Layer-2 aggregation fused with log_softmax.
// One warp per node; lane handles columns (lane) and (lane+32) of NCLASS=64.
// ---------------------------------------------------------------------------
__global__ __launch_bounds__(256)
void agg_lsm_kernel(const float* __restrict__ T, const int* __restrict__ edge,
                    float* __restrict__ out)
{
    const int gwarp = (blockIdx.x * blockDim.x + threadIdx.x) >> 5;
    const int lane  = threadIdx.x & 31;
    if (gwarp >= NN) return;

    const int node = gwarp;
    const int base = (node / NODE) * NODE;

    int e = (lane < DEG) ? edge[node * DEG + lane] : -1;

    // Dedup within warp: keep only the lowest lane holding each distinct id.
    unsigned m = __match_any_sync(0xffffffffu, e);
    bool keep = (lane < DEG) && (e >= 0) && ((m & ((1u << lane) - 1u)) == 0u);
    unsigned bm = __ballot_sync(0xffffffffu, keep);

    float a0 = 0.0f, a1 = 0.0f;
    while (bm) {
        int b = __ffs(bm) - 1;
        bm &= bm - 1;
        int j = __shfl_sync(0xffffffffu, e, b);
        const float* row = T + (size_t)(base + j) * NCLASS;
        a0 += row[lane];
        a1 += row[lane + 32];
    }

    // log_softmax across the 64 values held by this warp
    float mx = fmaxf(a0, a1);
#pragma unroll
    for (int o = 16; o; o >>= 1)
        mx = fmaxf(mx, __shfl_xor_sync(0xffffffffu, mx, o));
    float s = expf(a0 - mx) + expf(a1 - mx);
#pragma unroll
    for (int o = 16; o; o >>= 1)
        s += __shfl_xor_sync(0xffffffffu, s, o);
    float lse = logf(s) + mx;

    out[(size_t)node * NCLASS + lane]      = a0 - lse;
    out[(size_t)node * NCLASS + lane + 32] = a1 - lse;
}

// ---------------------------------------------------------------------------
extern "C" void kernel_launch(void* const* d_in, const int* in_sizes, int n_in,
                              void* d_out, int out_size)
{
    const float* x    = (const float*)d_in[0];  // [8192,128]
    const int*   edge = (const int*)  d_in[1];  // [8192,16]
    const float* W1   = (const float*)d_in[2];  // [128,256]
    const float* W2   = (const float*)d_in[3];  // [256,64]
    float* out = (float*)d_out;                 // [8192,64]

    float *gH, *gA, *gT;
    cudaGetSymbolAddress((void**)&gH, g_H);
    cudaGetSymbolAddress((void**)&gA, g_A);
    cudaGetSymbolAddress((void**)&gT, g_T);

    // H = x @ W1   [8192,256]
    sgemm_kernel<<<dim3(NN / BM, NHID / BN), 256>>>(x, W1, gH, NN, NHID, NFEAT);
    // h = relu(adj @ H)
    agg_relu_kernel<<<NN, 256>>>(gH, edge, gA);
    // T = h @ W2   [8192,64]
    sgemm_kernel<<<dim3(NN / BM, NCLASS / BN), 256>>>(gA, W2, gT, NN, NCLASS, NHID);
    // out = log_softmax(adj @ T)
    agg_lsm_kernel<<<(NN * 32) / 256, 256>>>(gT, edge, out);
}

// round 2
// speedup vs baseline: 1.4565x; 1.4565x over previous
#include <cuda_runtime.h>
#include <cuda_bf16.h>

#define NN      8192
#define NODE    256
#define DEG     16
#define NFEAT   128
#define NHID    256
#define NCLASS  64

// Scratch (device globals; allocation is forbidden)
__device__ float    g_X[NN * NFEAT];    // adj @ x
__device__ float    g_H[NN * NHID];     // relu(gX @ W1)
__device__ float    g_T[NN * NCLASS];   // gH @ W2
__device__ unsigned g_keep[NN];         // dedup bitmask per node (bits 0..15)

// ---------------------------------------------------------------------------
// Aggregate x with dedup (adj @ x), and emit per-node keep bitmask.
// One warp per node; lane = one float4 of the 128-wide row.
// ---------------------------------------------------------------------------
__global__ __launch_bounds__(256)
void agg_x_kernel(const float* __restrict__ x, const int* __restrict__ edge,
                  float* __restrict__ gX, unsigned* __restrict__ keep_out)
{
    const int node = (blockIdx.x * blockDim.x + threadIdx.x) >> 5;
    const int lane = threadIdx.x & 31;
    if (node >= NN) return;
    const int base = (node >> 8) << 8;   // (node / NODE) * NODE

    int e = (lane < DEG) ? edge[node * DEG + lane] : -1;

    // Dedup: keep only the lowest lane holding each distinct valid id.
    unsigned m = __match_any_sync(0xffffffffu, e);
    bool kp = (lane < DEG) && (e >= 0) && ((m & ((1u << lane) - 1u)) == 0u);
    unsigned mask = __ballot_sync(0xffffffffu, kp) & 0xffffu;
    if (lane == 0) keep_out[node] = mask;

    float4 acc = make_float4(0.f, 0.f, 0.f, 0.f);
#pragma unroll
    for (int t = 0; t < DEG; ++t) {
        int j = __shfl_sync(0xffffffffu, e, t);
        if (mask & (1u << t)) {
            float4 v = *reinterpret_cast<const float4*>(
                x + (size_t)(base + j) * NFEAT + (lane << 2));
            acc.x += v.x; acc.y += v.y; acc.z += v.z; acc.w += v.w;
        }
    }
    *reinterpret_cast<float4*>(gX + (size_t)node * NFEAT + (lane << 2)) = acc;
}

// ---------------------------------------------------------------------------
// Register-tiled SGEMM: C[M,N] = A[M,K] @ B[K,N], optional fused ReLU.
// BN=64, BK=16, 256 threads. BM_/TM_ templated (128/8 or 64/4).
// Requires M%BM_==0, N%64==0, K%16==0, 16B-aligned pointers.
// ---------------------------------------------------------------------------
template<int BM_, int TM_, bool RELU>
__global__ __launch_bounds__(256)
void sgemm(const float* __restrict__ A, const float* __restrict__ B,
           float* __restrict__ C, int M, int Nn, int K)
{
    constexpr int BN_ = 64, BK_ = 16;
    __shared__ float As[BK_][BM_ + 4];   // k-major (transposed on load)
    __shared__ float Bs[BK_][BN_];

    const int tid  = threadIdx.x;
    const int brow = blockIdx.x * BM_;
    const int bcol = blockIdx.y * BN_;
    const int tx = tid & 15;             // 4 cols each
    const int ty = tid >> 4;             // TM_ rows each

    float acc[TM_][4] = {};

    for (int k0 = 0; k0 < K; k0 += BK_) {
        // A tile: BM_ x 16, transposed into As
#pragma unroll
        for (int L = tid; L < (BM_ * BK_) / 4; L += 256) {
            int row = L >> 2;
            int cs  = (L & 3) << 2;
            float4 v = *reinterpret_cast<const float4*>(
                A + (size_t)(brow + row) * K + k0 + cs);
            As[cs + 0][row] = v.x;
            As[cs + 1][row] = v.y;
            As[cs + 2][row] = v.z;
            As[cs + 3][row] = v.w;
        }
        // B tile: 16 x 64 (one float4 per thread)
        {
            int row = tid >> 4;
            int col = (tid & 15) << 2;
            *reinterpret_cast<float4*>(&Bs[row][col]) =
                *reinterpret_cast<const float4*>(B + (size_t)(k0 + row) * Nn + bcol + col);
        }
        __syncthreads();

#pragma unroll
        for (int k = 0; k < BK_; ++k) {
            float a[TM_];
#pragma unroll
            for (int i = 0; i < TM_; i += 4) {
                float4 ra = *reinterpret_cast<const float4*>(&As[k][ty * TM_ + i]);
                a[i] = ra.x; a[i + 1] = ra.y; a[i + 2] = ra.z; a[i + 3] = ra.w;
            }
            float4 rb = *reinterpret_cast<const float4*>(&Bs[k][tx << 2]);
            float b[4] = {rb.x, rb.y, rb.z, rb.w};
#pragma unroll
            for (int i = 0; i < TM_; ++i)
#pragma unroll
                for (int j = 0; j < 4; ++j)
                    acc[i][j] = fmaf(a[i], b[j], acc[i][j]);
        }
        __syncthreads();
    }

#pragma unroll
    for (int i = 0; i < TM_; ++i) {
        float4 v;
        if (RELU) {
            v = make_float4(fmaxf(acc[i][0], 0.f), fmaxf(acc[i][1], 0.f),
                            fmaxf(acc[i][2], 0.f), fmaxf(acc[i][3], 0.f));
        } else {
            v = make_float4(acc[i][0], acc[i][1], acc[i][2], acc[i][3]);
        }
        *reinterpret_cast<float4*>(
            C + (size_t)(brow + ty * TM_ + i) * Nn + bcol + (tx << 2)) = v;
    }
}

// ---------------------------------------------------------------------------
// Layer-2 aggregation fused with log_softmax, using precomputed keep masks.
// One warp per node; lane handles columns (lane) and (lane+32).
// ---------------------------------------------------------------------------
__global__ __launch_bounds__(256)
void agg_lsm_kernel(const float* __restrict__ T, const int* __restrict__ edge,
                    const unsigned* __restrict__ keep_in, float* __restrict__ out)
{
    const int node = (blockIdx.x * blockDim.x + threadIdx.x) >> 5;
    const int lane = threadIdx.x & 31;
    if (node >= NN) return;
    const int base = (node >> 8) << 8;

    int e = (lane < DEG) ? edge[node * DEG + lane] : 0;
    unsigned mask = keep_in[node];

    float a0 = 0.0f, a1 = 0.0f;
#pragma unroll
    for (int t = 0; t < DEG; ++t) {
        int j = __shfl_sync(0xffffffffu, e, t);
        if (mask & (1u << t)) {
            const float* row = T + (size_t)(base + j) * NCLASS;
            a0 += row[lane];
            a1 += row[lane + 32];
        }
    }

    float mx = fmaxf(a0, a1);
#pragma unroll
    for (int o = 16; o; o >>= 1)
        mx = fmaxf(mx, __shfl_xor_sync(0xffffffffu, mx, o));
    float s = expf(a0 - mx) + expf(a1 - mx);
#pragma unroll
    for (int o = 16; o; o >>= 1)
        s += __shfl_xor_sync(0xffffffffu, s, o);
    float lse = logf(s) + mx;

    out[(size_t)node * NCLASS + lane]      = a0 - lse;
    out[(size_t)node * NCLASS + lane + 32] = a1 - lse;
}

// ---------------------------------------------------------------------------
extern "C" void kernel_launch(void* const* d_in, const int* in_sizes, int n_in,
                              void* d_out, int out_size)
{
    const float* x    = (const float*)d_in[0];  // [8192,128]
    const int*   edge = (const int*)  d_in[1];  // [8192,16]
    const float* W1   = (const float*)d_in[2];  // [128,256]
    const float* W2   = (const float*)d_in[3];  // [256,64]
    float* out = (float*)d_out;                 // [8192,64]

    float *gX, *gH, *gT;
    unsigned *gK;
    cudaGetSymbolAddress((void**)&gX, g_X);
    cudaGetSymbolAddress((void**)&gH, g_H);
    cudaGetSymbolAddress((void**)&gT, g_T);
    cudaGetSymbolAddress((void**)&gK, g_keep);

    // gX = adj @ x  (dedup'd), also emit keep masks
    agg_x_kernel<<<NN / 8, 256>>>(x, edge, gX, gK);
    // gH = relu(gX @ W1)   [8192,256]
    sgemm<128, 8, true><<<dim3(NN / 128, NHID / 64), 256>>>(gX, W1, gH, NN, NHID, NFEAT);
    // gT = gH @ W2         [8192,64]
    sgemm<64, 4, false><<<dim3(NN / 64, NCLASS / 64), 256>>>(gH, W2, gT, NN, NCLASS, NHID);
    // out = log_softmax(adj @ gT)
    agg_lsm_kernel<<<NN / 8, 256>>>(gT, edge, gK, out);
}

// round 4
// speedup vs baseline: 1.8051x; 1.2393x over previous
#include <cuda_runtime.h>
#include <cuda_bf16.h>
#include <cstdint>

#define NN      8192
#define NODE    256
#define DEG     16
#define NFEAT   128
#define NHID    256
#define NCLASS  64

// ---------------- device scratch (no allocation allowed) --------------------
__device__ float    g_X[NN * NFEAT];      // adj @ x
__device__ float    g_H[NN * NHID];       // relu((adj@x) @ W1)
__device__ float    g_T[NN * NCLASS];     // g_H @ W2
__device__ unsigned g_keep[NN];           // dedup bitmask per node
__device__ float    g_W1t[NHID * NFEAT];  // W1^T  [256,128]
__device__ float    g_W2t[NCLASS * NHID]; // W2^T  [64,256]

__device__ __forceinline__ uint32_t f2tf32(float a) {
    uint32_t u; asm("cvt.rna.tf32.f32 %0, %1;" : "=r"(u) : "f"(a)); return u;
}

__device__ __forceinline__ void mma_tf32(float c[4], const uint32_t a[4], const uint32_t b[2]) {
    asm volatile(
        "mma.sync.aligned.m16n8k8.row.col.f32.tf32.tf32.f32 "
        "{%0,%1,%2,%3}, {%4,%5,%6,%7}, {%8,%9}, {%0,%1,%2,%3};"
        : "+f"(c[0]), "+f"(c[1]), "+f"(c[2]), "+f"(c[3])
        : "r"(a[0]), "r"(a[1]), "r"(a[2]), "r"(a[3]), "r"(b[0]), "r"(b[1]));
}

// ---------------------------------------------------------------------------
// prep: agg_x (dedup'd adj @ x, keep masks) in blocks 0..1023,
//       W1^T in blocks 1024..1055, W2^T in blocks 1056..1071.
// ---------------------------------------------------------------------------
__global__ __launch_bounds__(256)
void prep_kernel(const float* __restrict__ x, const int* __restrict__ edge,
                 const float* __restrict__ W1, const float* __restrict__ W2,
                 float* __restrict__ gX, unsigned* __restrict__ keep_out,
                 float* __restrict__ W1t, float* __restrict__ W2t)
{
    const int bid = blockIdx.x;
    const int tid = threadIdx.x;
    if (bid < 1024) {
        const int node = (bid * 256 + tid) >> 5;
        const int lane = tid & 31;
        const int base = (node >> 8) << 8;
        int e = (lane < DEG) ? edge[node * DEG + lane] : -1;
        unsigned m = __match_any_sync(0xffffffffu, e);
        bool kp = (lane < DEG) && (e >= 0) && ((m & ((1u << lane) - 1u)) == 0u);
        unsigned mask = __ballot_sync(0xffffffffu, kp) & 0xffffu;
        if (lane == 0) keep_out[node] = mask;
        float4 acc = make_float4(0.f, 0.f, 0.f, 0.f);
#pragma unroll
        for (int t = 0; t < DEG; ++t) {
            int j = __shfl_sync(0xffffffffu, e, t);
            if (mask & (1u << t)) {
                float4 v = *reinterpret_cast<const float4*>(
                    x + (size_t)(base + j) * NFEAT + (lane << 2));
                acc.x += v.x; acc.y += v.y; acc.z += v.z; acc.w += v.w;
            }
        }
        *reinterpret_cast<float4*>(gX + (size_t)node * NFEAT + (lane << 2)) = acc;
    } else if (bid < 1024 + 32) {
        int idx = (bid - 1024) * 1024 + tid * 4;      // over 256*128
        int n = idx >> 7, k = idx & 127;
        float4 v;
        v.x = W1[(k + 0) * NHID + n]; v.y = W1[(k + 1) * NHID + n];
        v.z = W1[(k + 2) * NHID + n]; v.w = W1[(k + 3) * NHID + n];
        *reinterpret_cast<float4*>(W1t + idx) = v;
    } else {
        int idx = (bid - 1056) * 1024 + tid * 4;      // over 64*256
        int n = idx >> 8, k = idx & 255;
        float4 v;
        v.x = W2[(k + 0) * NCLASS + n]; v.y = W2[(k + 1) * NCLASS + n];
        v.z = W2[(k + 2) * NCLASS + n]; v.w = W2[(k + 3) * NCLASS + n];
        *reinterpret_cast<float4*>(W2t + idx) = v;
    }
}

// ---------------------------------------------------------------------------
// Warp-level tf32 mma.sync GEMM with 3xTF32 compensation.
// C[BM x BN per CTA] = A[M,K] @ Bt[N,K]^T   (A row-major, Bt row-major = B^T)
// 256 threads = 8 warps, warp tile WM x WN, K chunked by 32.
// smem layout: [row][k] with row stride 36 floats (conflict-free frag loads).
// ---------------------------------------------------------------------------
template<int BM, int BN, int KTOT, int WM, int WN, bool RELU>
__global__ __launch_bounds__(256)
void gemm_mma(const float* __restrict__ A, const float* __restrict__ Bt,
              float* __restrict__ C, int ldc)
{
    constexpr int LDS_   = 36;               // 32 k + 4 pad
    constexpr int NWN    = BN / WN;           // warps along N
    constexpr int MSUB   = WM / 16;
    constexpr int NSUB   = WN / 8;
    constexpr int NCHUNK = KTOT / 32;
    constexpr int A_FLT  = BM * LDS_;
    constexpr int B_FLT  = BN * LDS_;

    extern __shared__ float sm[];
    float* Ah = sm;
    float* Al = Ah + A_FLT;
    float* Bh = Al + A_FLT;
    float* Bl = Bh + B_FLT;

    const int tid   = threadIdx.x;
    const int wid   = tid >> 5;
    const int lane  = tid & 31;
    const int brow  = blockIdx.x * BM;
    const int bcol  = blockIdx.y * BN;
    const int warpM = (wid / NWN) * WM;
    const int warpN = (wid % NWN) * WN;
    const int grp   = lane >> 2;             // 0..7
    const int qk    = lane & 3;              // 0..3

    float acc[MSUB][NSUB][4] = {};

    for (int c = 0; c < NCHUNK; ++c) {
        // ---- stage A chunk (BM x 32) as tf32 hi/lo ----
#pragma unroll
        for (int i = tid; i < BM * 8; i += 256) {
            int r = i >> 3, f = (i & 7) << 2;
            float4 v = *reinterpret_cast<const float4*>(
                A + (size_t)(brow + r) * KTOT + c * 32 + f);
            float* ph = Ah + r * LDS_ + f;
            float* pl = Al + r * LDS_ + f;
            float hx = __uint_as_float(f2tf32(v.x));
            float hy = __uint_as_float(f2tf32(v.y));
            float hz = __uint_as_float(f2tf32(v.z));
            float hw = __uint_as_float(f2tf32(v.w));
            ph[0] = hx; ph[1] = hy; ph[2] = hz; ph[3] = hw;
            pl[0] = __uint_as_float(f2tf32(v.x - hx));
            pl[1] = __uint_as_float(f2tf32(v.y - hy));
            pl[2] = __uint_as_float(f2tf32(v.z - hz));
            pl[3] = __uint_as_float(f2tf32(v.w - hw));
        }
        // ---- stage B chunk (BN x 32) as tf32 hi/lo ----
#pragma unroll
        for (int i = tid; i < BN * 8; i += 256) {
            int r = i >> 3, f = (i & 7) << 2;
            float4 v = *reinterpret_cast<const float4*>(
                Bt + (size_t)(bcol + r) * KTOT + c * 32 + f);
            float* ph = Bh + r * LDS_ + f;
            float* pl = Bl + r * LDS_ + f;
            float hx = __uint_as_float(f2tf32(v.x));
            float hy = __uint_as_float(f2tf32(v.y));
            float hz = __uint_as_float(f2tf32(v.z));
            float hw = __uint_as_float(f2tf32(v.w));
            ph[0] = hx; ph[1] = hy; ph[2] = hz; ph[3] = hw;
            pl[0] = __uint_as_float(f2tf32(v.x - hx));
            pl[1] = __uint_as_float(f2tf32(v.y - hy));
            pl[2] = __uint_as_float(f2tf32(v.z - hz));
            pl[3] = __uint_as_float(f2tf32(v.w - hw));
        }
        __syncthreads();

#pragma unroll
        for (int ks = 0; ks < 4; ++ks) {
            const int kb = ks * 8;
            uint32_t afh[MSUB][4], afl[MSUB][4];
#pragma unroll
            for (int ms = 0; ms < MSUB; ++ms) {
                int r0 = (warpM + ms * 16 + grp) * LDS_ + kb + qk;
                int r1 = r0 + 8 * LDS_;
                afh[ms][0] = __float_as_uint(Ah[r0]);
                afh[ms][1] = __float_as_uint(Ah[r1]);
                afh[ms][2] = __float_as_uint(Ah[r0 + 4]);
                afh[ms][3] = __float_as_uint(Ah[r1 + 4]);
                afl[ms][0] = __float_as_uint(Al[r0]);
                afl[ms][1] = __float_as_uint(Al[r1]);
                afl[ms][2] = __float_as_uint(Al[r0 + 4]);
                afl[ms][3] = __float_as_uint(Al[r1 + 4]);
            }
            uint32_t bfh[NSUB][2], bfl[NSUB][2];
#pragma unroll
            for (int ns = 0; ns < NSUB; ++ns) {
                int b0 = (warpN + ns * 8 + grp) * LDS_ + kb + qk;
                bfh[ns][0] = __float_as_uint(Bh[b0]);
                bfh[ns][1] = __float_as_uint(Bh[b0 + 4]);
                bfl[ns][0] = __float_as_uint(Bl[b0]);
                bfl[ns][1] = __float_as_uint(Bl[b0 + 4]);
            }
#pragma unroll
            for (int ms = 0; ms < MSUB; ++ms)
#pragma unroll
                for (int ns = 0; ns < NSUB; ++ns) {
                    mma_tf32(acc[ms][ns], afh[ms], bfh[ns]);
                    mma_tf32(acc[ms][ns], afh[ms], bfl[ns]);
                    mma_tf32(acc[ms][ns], afl[ms], bfh[ns]);
                }
        }
        __syncthreads();
    }

    // ---- epilogue ----
#pragma unroll
    for (int ms = 0; ms < MSUB; ++ms) {
#pragma unroll
        for (int ns = 0; ns < NSUB; ++ns) {
            int row = brow + warpM + ms * 16 + grp;
            int col = bcol + warpN + ns * 8 + 2 * qk;
            float2 v0 = make_float2(acc[ms][ns][0], acc[ms][ns][1]);
            float2 v1 = make_float2(acc[ms][ns][2], acc[ms][ns][3]);
            if (RELU) {
                v0.x = fmaxf(v0.x, 0.f); v0.y = fmaxf(v0.y, 0.f);
                v1.x = fmaxf(v1.x, 0.f); v1.y = fmaxf(v1.y, 0.f);
            }
            *reinterpret_cast<float2*>(C + (size_t)row * ldc + col)       = v0;
            *reinterpret_cast<float2*>(C + (size_t)(row + 8) * ldc + col) = v1;
        }
    }
}

// ---------------------------------------------------------------------------
// Layer-2 aggregation fused with log_softmax (keep masks from prep).
// ---------------------------------------------------------------------------
__global__ __launch_bounds__(256)
void agg_lsm_kernel(const float* __restrict__ T, const int* __restrict__ edge,
                    const unsigned* __restrict__ keep_in, float* __restrict__ out)
{
    const int node = (blockIdx.x * blockDim.x + threadIdx.x) >> 5;
    const int lane = threadIdx.x & 31;
    if (node >= NN) return;
    const int base = (node >> 8) << 8;

    int e = (lane < DEG) ? edge[node * DEG + lane] : 0;
    unsigned mask = keep_in[node];

    float a0 = 0.0f, a1 = 0.0f;
#pragma unroll
    for (int t = 0; t < DEG; ++t) {
        int j = __shfl_sync(0xffffffffu, e, t);
        if (mask & (1u << t)) {
            const float* row = T + (size_t)(base + j) * NCLASS;
            a0 += row[lane];
            a1 += row[lane + 32];
        }
    }
    float mx = fmaxf(a0, a1);
#pragma unroll
    for (int o = 16; o; o >>= 1)
        mx = fmaxf(mx, __shfl_xor_sync(0xffffffffu, mx, o));
    float s = expf(a0 - mx) + expf(a1 - mx);
#pragma unroll
    for (int o = 16; o; o >>= 1)
        s += __shfl_xor_sync(0xffffffffu, s, o);
    float lse = logf(s) + mx;

    out[(size_t)node * NCLASS + lane]      = a0 - lse;
    out[(size_t)node * NCLASS + lane + 32] = a1 - lse;
}

// ---------------------------------------------------------------------------
extern "C" void kernel_launch(void* const* d_in, const int* in_sizes, int n_in,
                              void* d_out, int out_size)
{
    const float* x    = (const float*)d_in[0];
    const int*   edge = (const int*)  d_in[1];
    const float* W1   = (const float*)d_in[2];
    const float* W2   = (const float*)d_in[3];
    float* out = (float*)d_out;

    float *gX, *gH, *gT, *gW1t, *gW2t;
    unsigned *gK;
    cudaGetSymbolAddress((void**)&gX,   g_X);
    cudaGetSymbolAddress((void**)&gH,   g_H);
    cudaGetSymbolAddress((void**)&gT,   g_T);
    cudaGetSymbolAddress((void**)&gK,   g_keep);
    cudaGetSymbolAddress((void**)&gW1t, g_W1t);
    cudaGetSymbolAddress((void**)&gW2t, g_W2t);

    // GEMM1: BM=128,BN=128,K=128, warp tile 64x32  -> grid (64,2), smem 73728B
    // GEMM2: BM=64, BN=64, K=256, warp tile 32x16  -> grid (128,1), smem 36864B
    constexpr int SMEM1 = (128 + 128) * 36 * 4 * 2;
    constexpr int SMEM2 = (64 + 64) * 36 * 4 * 2;
    cudaFuncSetAttribute(gemm_mma<128, 128, 128, 64, 32, true>,
                         cudaFuncAttributeMaxDynamicSharedMemorySize, SMEM1);
    cudaFuncSetAttribute(gemm_mma<64, 64, 256, 32, 16, false>,
                         cudaFuncAttributeMaxDynamicSharedMemorySize, SMEM2);

    prep_kernel<<<1072, 256>>>(x, edge, W1, W2, gX, gK, gW1t, gW2t);
    gemm_mma<128, 128, 128, 64, 32, true>
        <<<dim3(64, 2), 256, SMEM1>>>(gX, gW1t, gH, NHID);
    gemm_mma<64, 64, 256, 32, 16, false>
        <<<dim3(128, 1), 256, SMEM2>>>(gH, gW2t, gT, NCLASS);
    agg_lsm_kernel<<<NN / 8, 256>>>(gT, edge, gK, out);
}